// round 12
// baseline (speedup 1.0000x reference)
#include <cuda_runtime.h>
#include <cstdint>

// BumpKNN R11 (= R10 re-bench; container infra failure last round):
// 3xTF32 mma.sync.m16n8k8, m16 per warp, 2 accumulation chains,
// __launch_bounds__(256,2) -> 2 CTAs/SM (R9 binder was occupancy:
// tensor=53% @ occ=12.5%, regs=200). Fused last-CTA bump finalize.

#define NQ      2048
#define ND      65536
#define STRIPS  16          // 2048 / 128 queries per CTA
#define SPLITS  18          // 16*18 = 288 CTAs ~ 2 per SM
#define NTILE   128         // points per smem tile
#define THREADS 256
#define KPAD    20          // floats per point row: conflict-free LDS

__device__ float g_partial[SPLITS * NQ];
__device__ unsigned int g_done;   // zero-init; reset by last CTA each run

__device__ __forceinline__ uint32_t f2tf(float x) {
    uint32_t r; asm("cvt.rna.tf32.f32 %0, %1;" : "=r"(r) : "f"(x)); return r;
}

__device__ __forceinline__ void mma8(float c[4], const uint32_t a[4],
                                     uint32_t b0, uint32_t b1) {
    asm("mma.sync.aligned.m16n8k8.row.col.f32.tf32.tf32.f32 "
        "{%0,%1,%2,%3}, {%4,%5,%6,%7}, {%8,%9}, {%0,%1,%2,%3};"
        : "+f"(c[0]), "+f"(c[1]), "+f"(c[2]), "+f"(c[3])
        : "r"(a[0]), "r"(a[1]), "r"(a[2]), "r"(a[3]), "r"(b0), "r"(b1));
}

// ---------------------------------------------------------------------------
__global__ void __launch_bounds__(THREADS, 2)
mma_kernel(const float* __restrict__ x, const float* __restrict__ data,
           float* __restrict__ out) {
    __shared__ __align__(16) float sBhi[2][NTILE][KPAD];
    __shared__ __align__(16) float sBlo[2][NTILE][KPAD];
    __shared__ __align__(8)  float sD2[2][NTILE];

    const int tid = threadIdx.x, lane = tid & 31, w = tid >> 5;
    const int strip = blockIdx.x, split = blockIdx.y;
    const int tiles = (split < 8) ? 29 : 28;       // 8*29 + 10*28 = 512 tiles
    const int tbase = (split < 8) ? 29 * split : 232 + 28 * (split - 8);

    const int g4 = lane >> 2, kc = lane & 3;
    const int qb = strip * 128 + w * 16;           // 16 query rows per warp

    // A fragments: -2*x tf32 hi/lo, 2 k-chunks (K=16).
    uint32_t ah[2][4], al[2][4];
#pragma unroll
    for (int c = 0; c < 2; c++)
#pragma unroll
        for (int j = 0; j < 4; j++) {
            int row = qb + g4 + (j & 1) * 8;
            int k   = c * 8 + kc + (j >> 1) * 4;
            float s = -2.f * __ldg(&x[(size_t)row * 16 + k]);
            uint32_t h = f2tf(s);
            ah[c][j] = h;
            al[c][j] = f2tf(s - __uint_as_float(h));
        }

    const float4* dv = reinterpret_cast<const float4*>(data);
    const bool loader = tid < NTILE;
    float4 r0, r1, r2, r3;

    // Convert prefetched point -> hi/lo tf32 rows + d2; block-wise to keep
    // the live register set small (budget: 2 CTAs/SM).
    auto stash = [&](int buf) {
        uint4* ph = reinterpret_cast<uint4*>(&sBhi[buf][tid][0]);
        uint4* pl = reinterpret_cast<uint4*>(&sBlo[buf][tid][0]);
        float d2 = 0.f;
        float4 blocks[4] = {r0, r1, r2, r3};
#pragma unroll
        for (int b = 0; b < 4; b++) {
            float v0 = blocks[b].x, v1 = blocks[b].y;
            float v2 = blocks[b].z, v3 = blocks[b].w;
            d2 = fmaf(v0, v0, d2); d2 = fmaf(v1, v1, d2);
            d2 = fmaf(v2, v2, d2); d2 = fmaf(v3, v3, d2);
            uint32_t h0 = f2tf(v0), h1 = f2tf(v1), h2 = f2tf(v2), h3 = f2tf(v3);
            ph[b] = make_uint4(h0, h1, h2, h3);
            pl[b] = make_uint4(f2tf(v0 - __uint_as_float(h0)),
                               f2tf(v1 - __uint_as_float(h1)),
                               f2tf(v2 - __uint_as_float(h2)),
                               f2tf(v3 - __uint_as_float(h3)));
        }
        sD2[buf][tid] = d2;
    };

    if (loader) {
        size_t p = (size_t)tbase * NTILE + tid;
        r0 = dv[p*4+0]; r1 = dv[p*4+1]; r2 = dv[p*4+2]; r3 = dv[p*4+3];
        stash(0);
    }
    __syncthreads();

    const float INF = 3.402823466e38f;
    float m0 = INF, m1 = INF, m2 = INF, m3 = INF;

    for (int t = 0; t < tiles; t++) {
        const int buf = t & 1;
        if (t + 1 < tiles && loader) {            // prefetch next tile
            size_t p = (size_t)(tbase + t + 1) * NTILE + tid;
            r0 = dv[p*4+0]; r1 = dv[p*4+1]; r2 = dv[p*4+2]; r3 = dv[p*4+3];
        }

        const float* bh_ = &sBhi[buf][0][0];
        const float* bl_ = &sBlo[buf][0][0];
        const float* d2_ = &sD2[buf][0];
#pragma unroll 4
        for (int it = 0; it < NTILE / 8; it++) {   // 16 n8 groups
            const int nb = it * 8;
            const uint32_t* rh = reinterpret_cast<const uint32_t*>(bh_ + (nb + g4) * KPAD);
            const uint32_t* rl = reinterpret_cast<const uint32_t*>(bl_ + (nb + g4) * KPAD);
            uint32_t bh0 = rh[kc],     bh1 = rh[kc + 4];
            uint32_t bh2 = rh[kc + 8], bh3 = rh[kc + 12];
            uint32_t bl0 = rl[kc],     bl1 = rl[kc + 4];
            uint32_t bl2 = rl[kc + 8], bl3 = rl[kc + 12];

            float2 dd = *reinterpret_cast<const float2*>(d2_ + nb + 2 * kc);

            // 2 independent chains (k-chunks); d2 folded into k0-chain init.
            float c0[4] = {dd.x, dd.y, dd.x, dd.y};
            float c1[4] = {0.f, 0.f, 0.f, 0.f};

            mma8(c0, ah[0], bh0, bh1);  mma8(c1, ah[1], bh2, bh3);  // hh
            mma8(c0, ah[0], bl0, bl1);  mma8(c1, ah[1], bl2, bl3);  // hl
            mma8(c0, al[0], bh0, bh1);  mma8(c1, al[1], bh2, bh3);  // lh

            m0 = fminf(m0, c0[0] + c1[0]);
            m1 = fminf(m1, c0[1] + c1[1]);
            m2 = fminf(m2, c0[2] + c1[2]);
            m3 = fminf(m3, c0[3] + c1[3]);
        }

        if (t + 1 < tiles && loader) stash((t + 1) & 1);
        __syncthreads();
    }

    // Row mins: c0/c1 -> row g4, c2/c3 -> row g4+8; reduce across the 4
    // kc-lanes sharing each row.
    float rA = fminf(m0, m1);
    float rB = fminf(m2, m3);
    rA = fminf(rA, __shfl_xor_sync(0xffffffffu, rA, 1));
    rA = fminf(rA, __shfl_xor_sync(0xffffffffu, rA, 2));
    rB = fminf(rB, __shfl_xor_sync(0xffffffffu, rB, 1));
    rB = fminf(rB, __shfl_xor_sync(0xffffffffu, rB, 2));
    if (kc == 0) {
        g_partial[split * NQ + qb + g4]     = rA;  // = min(d2 - 2*dot)
        g_partial[split * NQ + qb + g4 + 8] = rB;
    }

    // ---- fused finalize: last CTA to arrive does the bump epilogue ----
    __threadfence();
    __shared__ unsigned int sLast;
    __syncthreads();
    if (tid == 0) sLast = atomicAdd(&g_done, 1u);
    __syncthreads();
    if (sLast == STRIPS * SPLITS - 1) {
        __threadfence();
        for (int q = tid; q < NQ; q += THREADS) {
            const float4* xp = reinterpret_cast<const float4*>(x + (size_t)q * 16);
            float4 a = xp[0], b = xp[1], c = xp[2], d = xp[3];
            float x2 = a.x*a.x + a.y*a.y + a.z*a.z + a.w*a.w
                     + b.x*b.x + b.y*b.y + b.z*b.z + b.w*b.w
                     + c.x*c.x + c.y*c.y + c.z*c.z + c.w*c.w
                     + d.x*d.x + d.y*d.y + d.z*d.z + d.w*d.w;
            float m = INF;
#pragma unroll
            for (int s = 0; s < SPLITS; s++)
                m = fminf(m, g_partial[s * NQ + q]);

            float nn2  = fmaxf(x2 + m, 0.0f);          // clamp tiny negatives
            float d2c  = fmaxf(nn2, 1e-12f);
            float dist = sqrtf(d2c);
            float r = 0.0f;
            if (dist < 2.0f) {                          // RADIUS = 2
                float ds = dist * dist;                 // reference sqrt->square
                r = expf(1.0f / (ds - 4.0f) + 0.25f);   // DECAY/denom + DECAY/r^2
            }
            out[q] = r;
        }
        __syncthreads();
        if (tid == 0) g_done = 0;                       // reset for next replay
    }
}

// ---------------------------------------------------------------------------
extern "C" void kernel_launch(void* const* d_in, const int* in_sizes, int n_in,
                              void* d_out, int out_size) {
    const float* x    = (const float*)d_in[0];
    const float* data = (const float*)d_in[1];
    if (n_in >= 2 && in_sizes[0] > in_sizes[1]) {  // defensive order check
        x    = (const float*)d_in[1];
        data = (const float*)d_in[0];
    }

    dim3 grid(STRIPS, SPLITS);
    mma_kernel<<<grid, THREADS>>>(x, data, (float*)d_out);
}